// round 8
// baseline (speedup 1.0000x reference)
#include <cuda_runtime.h>
#include <cuda_fp16.h>
#include <cuda_fp8.h>
#include <math.h>
#include <stdint.h>

#define N_TOTAL 8192
#define HALF_N  4096
#define BM      128
#define BN      64
#define NBLK    128              // N_TOTAL / BN
#define NTILES  4160             // sum over bi of (128 - 2*bi)
#define NCTAS   456              // 3 per SM (152 SMs)
#define PITCHB  144              // 128B fp8 row + 16B pad

#define SMEM_A    0              // 128 * 144 = 18432
#define SMEM_B0   18432          // 64 * 144 = 9216
#define SMEM_B1   27648
#define SMEM_NI   36864          // 128 floats
#define SMEM_NJ0  37376          // 64 floats
#define SMEM_NJ1  37632
#define SMEM_TOTAL 37888

__device__ __align__(16) uint8_t g_Y[N_TOTAL * 128];   // 1 MB e4m3 copy
__device__ float g_norm[N_TOTAL];
__device__ float g_rowsum[N_TOTAL];
__device__ float g_diag[HALF_N];
__device__ int   g_done;

// ---------------------------------------------------------------- helpers
__device__ __forceinline__ uint32_t smem_u32(const void* p) {
    uint32_t a;
    asm("{ .reg .u64 t; cvta.to.shared.u64 t, %1; cvt.u32.u64 %0, t; }"
        : "=r"(a) : "l"(p));
    return a;
}
__device__ __forceinline__ void cp_async16(uint32_t dst, const void* src) {
    asm volatile("cp.async.cg.shared.global [%0], [%1], 16;"
                 :: "r"(dst), "l"(src) : "memory");
}
__device__ __forceinline__ void cp_commit() {
    asm volatile("cp.async.commit_group;" ::: "memory");
}
template <int N>
__device__ __forceinline__ void cp_wait() {
    asm volatile("cp.async.wait_group %0;" :: "n"(N) : "memory");
}
__device__ __forceinline__ void mma_fp8(float* c, const uint32_t* a, const uint32_t* b) {
    asm volatile(
        "mma.sync.aligned.m16n8k32.row.col.f32.e4m3.e4m3.f32 "
        "{%0,%1,%2,%3}, {%4,%5,%6,%7}, {%8,%9}, {%0,%1,%2,%3};"
        : "+f"(c[0]), "+f"(c[1]), "+f"(c[2]), "+f"(c[3])
        : "r"(a[0]), "r"(a[1]), "r"(a[2]), "r"(a[3]), "r"(b[0]), "r"(b[1]));
}
__device__ __forceinline__ void ldsm_x4(uint32_t* r, uint32_t addr) {
    asm volatile("ldmatrix.sync.aligned.m8n8.x4.shared.b16 {%0,%1,%2,%3}, [%4];"
                 : "=r"(r[0]), "=r"(r[1]), "=r"(r[2]), "=r"(r[3])
                 : "r"(addr));
}

// ---------------------------------------------------------------------------
// Kernel 1: pair-based prep. Warp w owns rows w and w+4096: loads each row
// once, computes both norms, the pair diag sim, fp8 packs, rowsum zero.
// ---------------------------------------------------------------------------
__global__ void prep_kernel(const float* __restrict__ X) {
    int w = (blockIdx.x * blockDim.x + threadIdx.x) >> 5;   // pair id 0..4095
    int lane = threadIdx.x & 31;
    if (blockIdx.x == 0 && threadIdx.x == 0) g_done = 0;
    if (w >= HALF_N) return;
    const float4* X4 = (const float4*)X;

    float4 v = X4[(size_t)w * 32 + lane];
    float4 u = X4[(size_t)(w + HALF_N) * 32 + lane];

    float s1 = v.x * v.x + v.y * v.y + v.z * v.z + v.w * v.w;
    float s2 = u.x * u.x + u.y * u.y + u.z * u.z + u.w * u.w;
    float dx = v.x - u.x, dy = v.y - u.y, dz = v.z - u.z, dw = v.w - u.w;
    float sq = dx * dx + dy * dy + dz * dz + dw * dw;
    #pragma unroll
    for (int off = 16; off; off >>= 1) {
        s1 += __shfl_xor_sync(0xffffffffu, s1, off);
        s2 += __shfl_xor_sync(0xffffffffu, s2, off);
        sq += __shfl_xor_sync(0xffffffffu, sq, off);
    }
    if (lane == 0) {
        g_norm[w] = s1;
        g_norm[w + HALF_N] = s2;
        g_rowsum[w] = 0.0f;
        g_rowsum[w + HALF_N] = 0.0f;
        g_diag[w] = 1.0f / (fmaxf(sq, 0.0f) + 1.0f);
    }

    uint32_t a0 = __nv_cvt_float_to_fp8(v.x, __NV_SATFINITE, __NV_E4M3);
    uint32_t a1 = __nv_cvt_float_to_fp8(v.y, __NV_SATFINITE, __NV_E4M3);
    uint32_t a2 = __nv_cvt_float_to_fp8(v.z, __NV_SATFINITE, __NV_E4M3);
    uint32_t a3 = __nv_cvt_float_to_fp8(v.w, __NV_SATFINITE, __NV_E4M3);
    ((uint32_t*)(g_Y + (size_t)w * 128))[lane] = a0 | (a1 << 8) | (a2 << 16) | (a3 << 24);
    uint32_t b0 = __nv_cvt_float_to_fp8(u.x, __NV_SATFINITE, __NV_E4M3);
    uint32_t b1 = __nv_cvt_float_to_fp8(u.y, __NV_SATFINITE, __NV_E4M3);
    uint32_t b2 = __nv_cvt_float_to_fp8(u.z, __NV_SATFINITE, __NV_E4M3);
    uint32_t b3 = __nv_cvt_float_to_fp8(u.w, __NV_SATFINITE, __NV_E4M3);
    ((uint32_t*)(g_Y + (size_t)(w + HALF_N) * 128))[lane] =
        b0 | (b1 << 8) | (b2 << 16) | (b3 << 24);
}

// ---------------------------------------------------------------------------
// Kernel 2: persistent 128x64-tile fp8 GEMM over upper-triangular col-blocks.
// 456 CTAs, 3/SM. Warp grid 4(m) x 2(n), warp tile 32x32 (acc=32 regs).
// Straddle tiles (bj64 in {2bi, 2bi+1}) mask i>j to 0 and i==j to row-only 1.
// Last CTA to finish computes the final scalar in-kernel.
// ---------------------------------------------------------------------------
__global__ void __launch_bounds__(256, 3)
simsum_kernel(float* __restrict__ out) {
    extern __shared__ char smem[];
    const uint32_t sb = smem_u32(smem);
    float* nIs = (float*)(smem + SMEM_NI);

    const int tid = threadIdx.x;
    const int wid = tid >> 5, lid = tid & 31;
    const int wm = wid >> 1, wn = wid & 1;     // warp grid 4x2
    const int g = lid >> 2, t = lid & 3;

    // chunking: 4160 = 456*9 + 56 -> first 56 CTAs get 10 tiles
    const int c = blockIdx.x;
    const int start = 9 * c + min(c, 56);
    const int cnt = 9 + (c < 56 ? 1 : 0);

    // decode: tiles before row-block b = b*(129-b)
    int cbi = 0;
    #pragma unroll 1
    while ((cbi + 1) * (129 - (cbi + 1)) <= start) ++cbi;
    int cbj = 2 * cbi + (start - cbi * (129 - cbi));

    const uint32_t arel = (uint32_t)((wm * 32 + (lid & 15)) * PITCHB + (lid >> 4) * 16);
    const uint32_t brel = (uint32_t)((wn * 32 + (lid >> 4) * 8 + (lid & 7)) * PITCHB
                                     + ((lid >> 3) & 1) * 16);

    // ---- initial loads: A(cbi) 128 rows, nIs, B0(cbj) 64 rows, nJ0 ----
    {
        const char* Yb = (const char*)g_Y;
        #pragma unroll
        for (int it = 0; it < 4; ++it) {
            int chunk = it * 256 + tid;            // 1024 chunks
            int r = chunk >> 3, cc = chunk & 7;
            cp_async16(sb + SMEM_A + r * PITCHB + cc * 16,
                       Yb + (size_t)(cbi * BM + r) * 128 + cc * 16);
        }
        #pragma unroll
        for (int it = 0; it < 2; ++it) {
            int chunk = it * 256 + tid;            // 512 chunks
            int r = chunk >> 3, cc = chunk & 7;
            cp_async16(sb + SMEM_B0 + r * PITCHB + cc * 16,
                       Yb + (size_t)(cbj * BN + r) * 128 + cc * 16);
        }
        if (tid < 32)
            cp_async16(sb + SMEM_NI + tid * 16, g_norm + cbi * BM + tid * 4);
        if (tid < 16)
            cp_async16(sb + SMEM_NJ0 + tid * 16, g_norm + cbj * BN + tid * 4);
        cp_commit();
    }

    #pragma unroll 1
    for (int it = 0; it < cnt; ++it) {
        const int buf = it & 1;
        const uint32_t bbase = buf ? SMEM_B1 : SMEM_B0;
        const uint32_t njoff = buf ? SMEM_NJ1 : SMEM_NJ0;
        const int row0 = cbi * BM, col0 = cbj * BN;
        const bool straddle = (cbj <= 2 * cbi + 1);

        cp_wait<0>();
        __syncthreads();

        // next tile; prefetch its B (+nJ)
        int nbi = cbi, nbj = cbj;
        bool rowchg = false;
        if (it + 1 < cnt) {
            if (cbj == NBLK - 1) { nbi = cbi + 1; nbj = 2 * nbi; rowchg = true; }
            else nbj = cbj + 1;
            const uint32_t nb = buf ? SMEM_B0 : SMEM_B1;
            const char* Yb = (const char*)g_Y;
            #pragma unroll
            for (int i2 = 0; i2 < 2; ++i2) {
                int chunk = i2 * 256 + tid;
                int r = chunk >> 3, cc = chunk & 7;
                cp_async16(sb + nb + r * PITCHB + cc * 16,
                           Yb + (size_t)(nbj * BN + r) * 128 + cc * 16);
            }
            if (tid < 16)
                cp_async16(sb + (buf ? SMEM_NJ0 : SMEM_NJ1) + tid * 16,
                           g_norm + nbj * BN + tid * 4);
            cp_commit();
        }

        // ---- MMA: 128x64, K=128 fp8, 4 k-steps ----
        float acc[2][4][4];
        #pragma unroll
        for (int mt = 0; mt < 2; ++mt)
            #pragma unroll
            for (int nt = 0; nt < 4; ++nt)
                #pragma unroll
                for (int e = 0; e < 4; ++e) acc[mt][nt][e] = 0.0f;

        const uint32_t aA = sb + SMEM_A + arel;
        const uint32_t aB = sb + bbase + brel;

        #pragma unroll
        for (int s = 0; s < 4; ++s) {
            const uint32_t kb = (uint32_t)(s * 32);
            uint32_t a[2][4], b[2][4];
            #pragma unroll
            for (int mt = 0; mt < 2; ++mt)
                ldsm_x4(a[mt], aA + mt * 16 * PITCHB + kb);
            #pragma unroll
            for (int p = 0; p < 2; ++p)
                ldsm_x4(b[p], aB + p * 16 * PITCHB + kb);
            #pragma unroll
            for (int mt = 0; mt < 2; ++mt) {
                mma_fp8(acc[mt][0], a[mt], &b[0][0]);
                mma_fp8(acc[mt][1], a[mt], &b[0][2]);
                mma_fp8(acc[mt][2], a[mt], &b[1][0]);
                mma_fp8(acc[mt][3], a[mt], &b[1][2]);
            }
        }

        // ---- epilogue ----
        const float* nJs = (const float*)(smem + njoff);
        float rs[2][2], cs[4][2];
        #pragma unroll
        for (int i = 0; i < 2; ++i) rs[i][0] = rs[i][1] = 0.0f;
        #pragma unroll
        for (int i = 0; i < 4; ++i) cs[i][0] = cs[i][1] = 0.0f;

        float cI[2][2], nJ[4][2];
        #pragma unroll
        for (int mt = 0; mt < 2; ++mt) {
            cI[mt][0] = nIs[wm * 32 + mt * 16 + g] + 1.0f;
            cI[mt][1] = nIs[wm * 32 + mt * 16 + g + 8] + 1.0f;
        }
        #pragma unroll
        for (int nt = 0; nt < 4; ++nt) {
            nJ[nt][0] = nJs[wn * 32 + nt * 8 + 2 * t];
            nJ[nt][1] = nJs[wn * 32 + nt * 8 + 2 * t + 1];
        }

        if (!straddle) {
            #pragma unroll
            for (int mt = 0; mt < 2; ++mt)
                #pragma unroll
                for (int nt = 0; nt < 4; ++nt)
                    #pragma unroll
                    for (int r = 0; r < 2; ++r)
                        #pragma unroll
                        for (int e = 0; e < 2; ++e) {
                            float sqp1 = fmaf(-2.0f, acc[mt][nt][r * 2 + e],
                                              cI[mt][r] + nJ[nt][e]);
                            float sim = __fdividef(1.0f, sqp1);
                            rs[mt][r] += sim;
                            cs[nt][e] += sim;
                        }
        } else {
            #pragma unroll
            for (int mt = 0; mt < 2; ++mt)
                #pragma unroll
                for (int nt = 0; nt < 4; ++nt)
                    #pragma unroll
                    for (int r = 0; r < 2; ++r)
                        #pragma unroll
                        for (int e = 0; e < 2; ++e) {
                            int gi = row0 + wm * 32 + mt * 16 + g + r * 8;
                            int gj = col0 + wn * 32 + nt * 8 + 2 * t + e;
                            float sqp1 = fmaf(-2.0f, acc[mt][nt][r * 2 + e],
                                              cI[mt][r] + nJ[nt][e]);
                            float sim = __fdividef(1.0f, sqp1);
                            float simr = sim, simc = sim;
                            if (gi > gj) { simr = 0.0f; simc = 0.0f; }
                            if (gi == gj) { simr = 1.0f; simc = 0.0f; }
                            rs[mt][r] += simr;
                            cs[nt][e] += simc;
                        }
        }

        #pragma unroll
        for (int mt = 0; mt < 2; ++mt)
            #pragma unroll
            for (int r = 0; r < 2; ++r) {
                float v = rs[mt][r];
                v += __shfl_xor_sync(0xffffffffu, v, 1);
                v += __shfl_xor_sync(0xffffffffu, v, 2);
                if (t == 0)
                    atomicAdd(&g_rowsum[row0 + wm * 32 + mt * 16 + g + r * 8], v);
            }
        #pragma unroll
        for (int nt = 0; nt < 4; ++nt)
            #pragma unroll
            for (int e = 0; e < 2; ++e) {
                float v = cs[nt][e];
                v += __shfl_xor_sync(0xffffffffu, v, 4);
                v += __shfl_xor_sync(0xffffffffu, v, 8);
                v += __shfl_xor_sync(0xffffffffu, v, 16);
                if (g == 0)
                    atomicAdd(&g_rowsum[col0 + wn * 32 + nt * 8 + 2 * t + e], v);
            }

        // row change: reload A + nIs
        if (rowchg) {
            __syncthreads();
            const char* Yb = (const char*)g_Y;
            #pragma unroll
            for (int i2 = 0; i2 < 4; ++i2) {
                int chunk = i2 * 256 + tid;
                int r = chunk >> 3, cc = chunk & 7;
                cp_async16(sb + SMEM_A + r * PITCHB + cc * 16,
                           Yb + (size_t)(nbi * BM + r) * 128 + cc * 16);
            }
            if (tid < 32)
                cp_async16(sb + SMEM_NI + tid * 16, g_norm + nbi * BM + tid * 4);
            cp_commit();
        }
        cbi = nbi; cbj = nbj;
    }

    // ---- last-CTA finalize ----
    __threadfence();
    __shared__ int s_last;
    __syncthreads();
    if (tid == 0) s_last = (atomicAdd(&g_done, 1) == NCTAS - 1);
    __syncthreads();
    if (!s_last) return;

    float* red = (float*)smem;     // 3 x 256 floats
    float tA = 0.0f, t1 = 0.0f, t2 = 0.0f;
    for (int i = tid; i < HALF_N; i += 256) {
        tA += __logf(g_diag[i]);
        t2 += __logf(__ldcg(&g_rowsum[i]) - 1.0f);
        t1 += __logf(__ldcg(&g_rowsum[i + HALF_N]) - 1.0f);
    }
    red[tid] = tA; red[256 + tid] = t1; red[512 + tid] = t2;
    __syncthreads();
    for (int s = 128; s; s >>= 1) {
        if (tid < s) {
            red[tid] += red[tid + s];
            red[256 + tid] += red[256 + tid + s];
            red[512 + tid] += red[512 + tid + s];
        }
        __syncthreads();
    }
    if (tid == 0) {
        float align = red[0] * (1.0f / HALF_N);
        float lse1  = red[256] * (1.0f / HALF_N);
        float lse2  = red[512] * (1.0f / HALF_N);
        out[0] = -(align - 0.5f * (lse1 + lse2));
    }
}

// ---------------------------------------------------------------------------
extern "C" void kernel_launch(void* const* d_in, const int* in_sizes, int n_in,
                              void* d_out, int out_size) {
    const float* X = (const float*)d_in[0];
    float* out = (float*)d_out;

    cudaFuncSetAttribute(simsum_kernel,
                         cudaFuncAttributeMaxDynamicSharedMemorySize, SMEM_TOTAL);

    prep_kernel<<<HALF_N / 8, 256>>>(X);
    simsum_kernel<<<NCTAS, 256, SMEM_TOTAL>>>(out);
}

// round 9
// speedup vs baseline: 1.0665x; 1.0665x over previous
#include <cuda_runtime.h>
#include <cuda_fp16.h>
#include <cuda_fp8.h>
#include <math.h>
#include <stdint.h>

#define N_TOTAL 8192
#define HALF_N  4096
#define BM      128
#define BN      128
#define MTILES  64               // N_TOTAL / BM
#define NCTAS   304              // 2 per SM
#define PITCHB  144              // 128B fp8 row + 16B pad

#define SMEM_A     0             // 128*144 = 18432
#define SMEM_B     18432         // 3 bufs of 18432 -> ends 73728
#define SMEM_NI    73728         // 512 B
#define SMEM_NJ    74240         // 3 bufs of 512 -> ends 75776
#define SMEM_TOTAL 75776

__device__ __align__(16) uint8_t g_Y[N_TOTAL * 128];   // 1 MB e4m3 copy
__device__ float g_norm[N_TOTAL];
__device__ float g_rowsum[N_TOTAL];
__device__ float g_diag[HALF_N];
__device__ int   g_done;

// ---------------------------------------------------------------- helpers
__device__ __forceinline__ uint32_t smem_u32(const void* p) {
    uint32_t a;
    asm("{ .reg .u64 t; cvta.to.shared.u64 t, %1; cvt.u32.u64 %0, t; }"
        : "=r"(a) : "l"(p));
    return a;
}
__device__ __forceinline__ void cp_async16(uint32_t dst, const void* src) {
    asm volatile("cp.async.cg.shared.global [%0], [%1], 16;"
                 :: "r"(dst), "l"(src) : "memory");
}
__device__ __forceinline__ void cp_commit() {
    asm volatile("cp.async.commit_group;" ::: "memory");
}
template <int N>
__device__ __forceinline__ void cp_wait() {
    asm volatile("cp.async.wait_group %0;" :: "n"(N) : "memory");
}
__device__ __forceinline__ void mma_fp8(float* c, const uint32_t* a, const uint32_t* b) {
    asm volatile(
        "mma.sync.aligned.m16n8k32.row.col.f32.e4m3.e4m3.f32 "
        "{%0,%1,%2,%3}, {%4,%5,%6,%7}, {%8,%9}, {%0,%1,%2,%3};"
        : "+f"(c[0]), "+f"(c[1]), "+f"(c[2]), "+f"(c[3])
        : "r"(a[0]), "r"(a[1]), "r"(a[2]), "r"(a[3]), "r"(b[0]), "r"(b[1]));
}
__device__ __forceinline__ void ldsm_x4(uint32_t* r, uint32_t addr) {
    asm volatile("ldmatrix.sync.aligned.m8n8.x4.shared.b16 {%0,%1,%2,%3}, [%4];"
                 : "=r"(r[0]), "=r"(r[1]), "=r"(r[2]), "=r"(r[3])
                 : "r"(addr));
}

// ---------------------------------------------------------------------------
// Kernel 1: pair-based prep (each row loaded once).
// ---------------------------------------------------------------------------
__global__ void prep_kernel(const float* __restrict__ X) {
    int w = (blockIdx.x * blockDim.x + threadIdx.x) >> 5;   // pair id
    int lane = threadIdx.x & 31;
    if (blockIdx.x == 0 && threadIdx.x == 0) g_done = 0;
    if (w >= HALF_N) return;
    const float4* X4 = (const float4*)X;

    float4 v = X4[(size_t)w * 32 + lane];
    float4 u = X4[(size_t)(w + HALF_N) * 32 + lane];

    float s1 = v.x * v.x + v.y * v.y + v.z * v.z + v.w * v.w;
    float s2 = u.x * u.x + u.y * u.y + u.z * u.z + u.w * u.w;
    float dx = v.x - u.x, dy = v.y - u.y, dz = v.z - u.z, dw = v.w - u.w;
    float sq = dx * dx + dy * dy + dz * dz + dw * dw;
    #pragma unroll
    for (int off = 16; off; off >>= 1) {
        s1 += __shfl_xor_sync(0xffffffffu, s1, off);
        s2 += __shfl_xor_sync(0xffffffffu, s2, off);
        sq += __shfl_xor_sync(0xffffffffu, sq, off);
    }
    if (lane == 0) {
        g_norm[w] = s1;
        g_norm[w + HALF_N] = s2;
        g_rowsum[w] = 0.0f;
        g_rowsum[w + HALF_N] = 0.0f;
        g_diag[w] = 1.0f / (fmaxf(sq, 0.0f) + 1.0f);
    }

    uint32_t a0 = __nv_cvt_float_to_fp8(v.x, __NV_SATFINITE, __NV_E4M3);
    uint32_t a1 = __nv_cvt_float_to_fp8(v.y, __NV_SATFINITE, __NV_E4M3);
    uint32_t a2 = __nv_cvt_float_to_fp8(v.z, __NV_SATFINITE, __NV_E4M3);
    uint32_t a3 = __nv_cvt_float_to_fp8(v.w, __NV_SATFINITE, __NV_E4M3);
    ((uint32_t*)(g_Y + (size_t)w * 128))[lane] = a0 | (a1 << 8) | (a2 << 16) | (a3 << 24);
    uint32_t b0 = __nv_cvt_float_to_fp8(u.x, __NV_SATFINITE, __NV_E4M3);
    uint32_t b1 = __nv_cvt_float_to_fp8(u.y, __NV_SATFINITE, __NV_E4M3);
    uint32_t b2 = __nv_cvt_float_to_fp8(u.z, __NV_SATFINITE, __NV_E4M3);
    uint32_t b3 = __nv_cvt_float_to_fp8(u.w, __NV_SATFINITE, __NV_E4M3);
    ((uint32_t*)(g_Y + (size_t)(w + HALF_N) * 128))[lane] =
        b0 | (b1 << 8) | (b2 << 16) | (b3 << 24);
}

__device__ __forceinline__ void adv(int& bi, int& bj) {
    if (bj == MTILES - 1) { ++bi; bj = bi; } else ++bj;
}
__device__ __forceinline__ void load_B(uint32_t sb, int pb, int bj, int tid) {
    const char* Yb = (const char*)g_Y;
    const uint32_t dst = sb + SMEM_B + pb * 18432;
    #pragma unroll
    for (int i2 = 0; i2 < 4; ++i2) {
        int chunk = i2 * 256 + tid;
        int r = chunk >> 3, cc = chunk & 7;
        cp_async16(dst + r * PITCHB + cc * 16,
                   Yb + (size_t)(bj * BN + r) * 128 + cc * 16);
    }
    if (tid < 32)
        cp_async16(sb + SMEM_NJ + pb * 512 + tid * 16, g_norm + bj * BN + tid * 4);
}
__device__ __forceinline__ void load_A(uint32_t sb, int bi, int tid) {
    const char* Yb = (const char*)g_Y;
    #pragma unroll
    for (int i2 = 0; i2 < 4; ++i2) {
        int chunk = i2 * 256 + tid;
        int r = chunk >> 3, cc = chunk & 7;
        cp_async16(sb + SMEM_A + r * PITCHB + cc * 16,
                   Yb + (size_t)(bi * BM + r) * 128 + cc * 16);
    }
    if (tid < 32)
        cp_async16(sb + SMEM_NI + tid * 16, g_norm + bi * BM + tid * 4);
}

// ---------------------------------------------------------------------------
// Kernel 2: persistent triangular fp8 GEMM, triple-buffered B, one barrier
// per tile, register-resident row sums across each row run.
// ---------------------------------------------------------------------------
__global__ void __launch_bounds__(256, 2)
simsum_kernel(float* __restrict__ out) {
    extern __shared__ char smem[];
    const uint32_t sb = smem_u32(smem);
    float* nIs = (float*)(smem + SMEM_NI);

    const int tid = threadIdx.x;
    const int lid = tid & 31;
    const int wid = tid >> 5;
    const int wm = wid >> 2, wn = wid & 3;     // 2(m) x 4(n)
    const int g = lid >> 2, t = lid & 3;

    const int c = blockIdx.x;
    const int start = 6 * c + min(c, 256);     // 2080 = 256*7 + 48*6
    const int cnt = 6 + (c < 256 ? 1 : 0);

    int bi = 0;
    #pragma unroll 1
    while ((bi + 1) * (129 - (bi + 1)) / 2 <= start) ++bi;
    int bj = bi + (start - bi * (129 - bi) / 2);

    const uint32_t arel = (uint32_t)((wm * 64 + (lid & 15)) * PITCHB + (lid >> 4) * 16);
    const uint32_t brel = (uint32_t)((wn * 32 + (lid >> 4) * 8 + (lid & 7)) * PITCHB
                                     + ((lid >> 3) & 1) * 16);

    load_A(sb, bi, tid);
    load_B(sb, 0, bj, tid);
    cp_commit();
    if (cnt > 1) {
        int b1i = bi, b1j = bj; adv(b1i, b1j);
        load_B(sb, 1, b1j, tid);
    }
    cp_commit();

    float rs[4][2];                            // persistent row sums (8 rows)
    #pragma unroll
    for (int i = 0; i < 4; ++i) rs[i][0] = rs[i][1] = 0.0f;
    bool waitAll = false;

    #pragma unroll 1
    for (int it = 0; it < cnt; ++it) {
        const int buf = it - (it / 3) * 3;
        const int row0 = bi * BM, col0 = bj * BN;
        const bool isdiag = (bi == bj);

        if (waitAll) cp_wait<0>(); else cp_wait<1>();
        __syncthreads();
        waitAll = false;

        int b1i = bi, b1j = bj; adv(b1i, b1j);
        if (it + 2 < cnt) {
            int b2i = b1i, b2j = b1j; adv(b2i, b2j);
            int pb = (it + 2) - ((it + 2) / 3) * 3;
            load_B(sb, pb, b2j, tid);
        }
        cp_commit();

        // ---- MMA ----
        float acc[4][4][4];
        #pragma unroll
        for (int mt = 0; mt < 4; ++mt)
            #pragma unroll
            for (int nt = 0; nt < 4; ++nt)
                #pragma unroll
                for (int e = 0; e < 4; ++e) acc[mt][nt][e] = 0.0f;

        const uint32_t aA = sb + SMEM_A + arel;
        const uint32_t aB = sb + SMEM_B + buf * 18432 + brel;

        #pragma unroll
        for (int s = 0; s < 4; ++s) {
            const uint32_t kb = (uint32_t)(s * 32);
            uint32_t a[4][4], b[2][4];
            #pragma unroll
            for (int mt = 0; mt < 4; ++mt)
                ldsm_x4(a[mt], aA + mt * 16 * PITCHB + kb);
            #pragma unroll
            for (int p = 0; p < 2; ++p)
                ldsm_x4(b[p], aB + p * 16 * PITCHB + kb);
            #pragma unroll
            for (int mt = 0; mt < 4; ++mt) {
                mma_fp8(acc[mt][0], a[mt], &b[0][0]);
                mma_fp8(acc[mt][1], a[mt], &b[0][2]);
                mma_fp8(acc[mt][2], a[mt], &b[1][0]);
                mma_fp8(acc[mt][3], a[mt], &b[1][2]);
            }
        }

        // ---- epilogue ----
        const float* nJs = (const float*)(smem + SMEM_NJ + buf * 512);
        float cs[4][2];
        #pragma unroll
        for (int i = 0; i < 4; ++i) cs[i][0] = cs[i][1] = 0.0f;

        float nJ[4][2];
        #pragma unroll
        for (int nt = 0; nt < 4; ++nt) {
            nJ[nt][0] = nJs[wn * 32 + nt * 8 + 2 * t];
            nJ[nt][1] = nJs[wn * 32 + nt * 8 + 2 * t + 1];
        }

        #pragma unroll
        for (int mt = 0; mt < 4; ++mt) {
            float cI0 = nIs[wm * 64 + mt * 16 + g] + 1.0f;
            float cI1 = nIs[wm * 64 + mt * 16 + g + 8] + 1.0f;
            float r0 = 0.0f, r1 = 0.0f;
            #pragma unroll
            for (int nt = 0; nt < 4; ++nt) {
                #pragma unroll
                for (int e = 0; e < 2; ++e) {
                    float s0 = __fdividef(1.0f, fmaf(-2.0f, acc[mt][nt][e],     cI0 + nJ[nt][e]));
                    float s1 = __fdividef(1.0f, fmaf(-2.0f, acc[mt][nt][2 + e], cI1 + nJ[nt][e]));
                    if (isdiag) {
                        int li0 = wm * 64 + mt * 16 + g;
                        int lj = wn * 32 + nt * 8 + 2 * t + e;
                        if (li0 == lj) s0 = 1.0f;
                        if (li0 + 8 == lj) s1 = 1.0f;
                    }
                    r0 += s0; r1 += s1;
                    cs[nt][e] += s0 + s1;
                }
            }
            rs[mt][0] += r0; rs[mt][1] += r1;
        }

        if (!isdiag) {
            #pragma unroll
            for (int nt = 0; nt < 4; ++nt)
                #pragma unroll
                for (int e = 0; e < 2; ++e) {
                    float v = cs[nt][e];
                    v += __shfl_xor_sync(0xffffffffu, v, 4);
                    v += __shfl_xor_sync(0xffffffffu, v, 8);
                    v += __shfl_xor_sync(0xffffffffu, v, 16);
                    if (g == 0)
                        atomicAdd(&g_rowsum[col0 + wn * 32 + nt * 8 + 2 * t + e], v);
                }
        }

        const bool rowchg = (it + 1 < cnt) && (b1i != bi);
        if (rowchg || it == cnt - 1) {
            #pragma unroll
            for (int mt = 0; mt < 4; ++mt)
                #pragma unroll
                for (int r = 0; r < 2; ++r) {
                    float v = rs[mt][r];
                    v += __shfl_xor_sync(0xffffffffu, v, 1);
                    v += __shfl_xor_sync(0xffffffffu, v, 2);
                    if (t == 0)
                        atomicAdd(&g_rowsum[row0 + wm * 64 + mt * 16 + g + r * 8], v);
                    rs[mt][r] = 0.0f;
                }
        }

        if (rowchg) {
            __syncthreads();
            load_A(sb, b1i, tid);
            cp_commit();
            waitAll = true;
        }
        bi = b1i; bj = b1j;
    }

    // ---- last-CTA finalize ----
    __threadfence();
    __shared__ int s_last;
    __syncthreads();
    if (tid == 0) s_last = (atomicAdd(&g_done, 1) == NCTAS - 1);
    __syncthreads();
    if (!s_last) return;

    float* red = (float*)smem;
    float tA = 0.0f, t1 = 0.0f, t2 = 0.0f;
    for (int i = tid; i < HALF_N; i += 256) {
        tA += __logf(g_diag[i]);
        t2 += __logf(__ldcg(&g_rowsum[i]) - 1.0f);
        t1 += __logf(__ldcg(&g_rowsum[i + HALF_N]) - 1.0f);
    }
    red[tid] = tA; red[256 + tid] = t1; red[512 + tid] = t2;
    __syncthreads();
    for (int s = 128; s; s >>= 1) {
        if (tid < s) {
            red[tid] += red[tid + s];
            red[256 + tid] += red[256 + tid + s];
            red[512 + tid] += red[512 + tid + s];
        }
        __syncthreads();
    }
    if (tid == 0) {
        float align = red[0] * (1.0f / HALF_N);
        float lse1  = red[256] * (1.0f / HALF_N);
        float lse2  = red[512] * (1.0f / HALF_N);
        out[0] = -(align - 0.5f * (lse1 + lse2));
    }
}

// ---------------------------------------------------------------------------
extern "C" void kernel_launch(void* const* d_in, const int* in_sizes, int n_in,
                              void* d_out, int out_size) {
    const float* X = (const float*)d_in[0];
    float* out = (float*)d_out;

    cudaFuncSetAttribute(simsum_kernel,
                         cudaFuncAttributeMaxDynamicSharedMemorySize, SMEM_TOTAL);

    prep_kernel<<<HALF_N / 8, 256>>>(X);
    simsum_kernel<<<NCTAS, 256, SMEM_TOTAL>>>(out);
}